// round 1
// baseline (speedup 1.0000x reference)
#include <cuda_runtime.h>
#include <math.h>

// IMU feature extractor.
// in : (256, 7, 8192) f32   channels: ax ay az qw qx qy qz
// out: (256, 16, 8192) f32  channels: [imu 0-6][linacc 7-9][lam 10][jerk 11][angvel 12-14][angdist 15]

#define NB   256
#define TT   8192
#define TOLF 1e-8f
#define INV_DT 200.0f

__global__ __launch_bounds__(256)
void imu_feat_kernel(const float* __restrict__ in, float* __restrict__ out) {
    const int vpb = TT / 4;  // 2048 float4 vectors per batch-channel
    int tid = blockIdx.x * blockDim.x + threadIdx.x;
    if (tid >= NB * vpb) return;
    int b  = tid / vpb;
    int t0 = (tid - b * vpb) * 4;

    const float* pin  = in  + (size_t)b * 7  * TT;
    float*       pout = out + (size_t)b * 16 * TT;

    // ---- loads: center float4 per channel + scalar halos ----
    float4 AX = *(const float4*)(pin + 0 * TT + t0);
    float4 AY = *(const float4*)(pin + 1 * TT + t0);
    float4 AZ = *(const float4*)(pin + 2 * TT + t0);
    float4 QW = *(const float4*)(pin + 3 * TT + t0);
    float4 QX = *(const float4*)(pin + 4 * TT + t0);
    float4 QY = *(const float4*)(pin + 5 * TT + t0);
    float4 QZ = *(const float4*)(pin + 6 * TT + t0);

    int tm = (t0 > 0) ? t0 - 1 : 0;          // halo for lam[t-1] (unused at t==0)
    int tp = (t0 + 4 < TT) ? t0 + 4 : TT - 1; // shift_next clamp

    // time index j: 0 -> t0-1, 1..4 -> t0..t0+3, 5 -> t0+4
    float ax[5], ay[5], az[5];
    float qw[6], qx[6], qy[6], qz[6];

    ax[0] = pin[0 * TT + tm]; ay[0] = pin[1 * TT + tm]; az[0] = pin[2 * TT + tm];
    qw[0] = pin[3 * TT + tm]; qx[0] = pin[4 * TT + tm];
    qy[0] = pin[5 * TT + tm]; qz[0] = pin[6 * TT + tm];
    qw[5] = pin[3 * TT + tp]; qx[5] = pin[4 * TT + tp];
    qy[5] = pin[5 * TT + tp]; qz[5] = pin[6 * TT + tp];

    ax[1] = AX.x; ax[2] = AX.y; ax[3] = AX.z; ax[4] = AX.w;
    ay[1] = AY.x; ay[2] = AY.y; ay[3] = AY.z; ay[4] = AY.w;
    az[1] = AZ.x; az[2] = AZ.y; az[3] = AZ.z; az[4] = AZ.w;
    qw[1] = QW.x; qw[2] = QW.y; qw[3] = QW.z; qw[4] = QW.w;
    qx[1] = QX.x; qx[2] = QX.y; qx[3] = QX.z; qx[4] = QX.w;
    qy[1] = QY.x; qy[2] = QY.y; qy[3] = QY.z; qy[4] = QY.w;
    qz[1] = QZ.x; qz[2] = QZ.y; qz[3] = QZ.z; qz[4] = QZ.w;

    // ---- normalize quaternions (safe-div semantics: /1 when invalid) ----
    float nw[6], nx[6], ny[6], nz[6];
    bool  vq[6];
#pragma unroll
    for (int j = 0; j < 6; j++) {
        float n = sqrtf(qx[j] * qx[j] + qy[j] * qy[j] + qz[j] * qz[j] + qw[j] * qw[j]);
        bool  v = n > TOLF;
        float inv = v ? (1.0f / n) : 1.0f;
        nx[j] = qx[j] * inv; ny[j] = qy[j] * inv;
        nz[j] = qz[j] * inv; nw[j] = qw[j] * inv;
        vq[j] = v;
    }

    // ---- gravity removal + linear-acc magnitude (j = 0..4 -> t0-1..t0+3) ----
    float lam[5], lx[5], ly[5], lz[5];
#pragma unroll
    for (int j = 0; j < 5; j++) {
        float gx = 19.62f * (nx[j] * nz[j] - nw[j] * ny[j]);
        float gy = 19.62f * (nw[j] * nx[j] + ny[j] * nz[j]);
        float gz = 9.81f - 19.62f * (nx[j] * nx[j] + ny[j] * ny[j]);
        float vx = vq[j] ? (ax[j] - gx) : ax[j];
        float vy = vq[j] ? (ay[j] - gy) : ay[j];
        float vz = vq[j] ? (az[j] - gz) : az[j];
        lx[j] = vx; ly[j] = vy; lz[j] = vz;
        lam[j] = sqrtf(vx * vx + vy * vy + vz * vz);
    }

    // ---- per-output-element features (i = 0..3 -> t = t0+i) ----
    float jrk[4], wxo[4], wyo[4], wzo[4], adst[4];
#pragma unroll
    for (int i = 0; i < 4; i++) {
        int t = t0 + i;
        jrk[i] = (t > 0) ? (lam[i + 1] - lam[i]) : 0.0f;

        const int a = i + 1, c = i + 2;  // q(t), q(t+1)
        float dot = nx[a] * nx[c] + ny[a] * ny[c] + nz[a] * nz[c] + nw[a] * nw[c];
        float s   = (dot < 0.0f) ? -1.0f : 1.0f;
        float x2 = nx[c] * s, y2 = ny[c] * s, z2 = nz[c] * s, w2 = nw[c] * s;

        float dx = nw[a] * x2 - nx[a] * w2 - ny[a] * z2 + nz[a] * y2;
        float dy = nw[a] * y2 + nx[a] * z2 - ny[a] * w2 - nz[a] * x2;
        float dz = nw[a] * z2 - nx[a] * y2 + ny[a] * x2 - nz[a] * w2;
        float dw = nw[a] * w2 + nx[a] * x2 + ny[a] * y2 + nz[a] * z2;

        float vn  = sqrtf(dx * dx + dy * dy + dz * dz);
        float dwc = fminf(fmaxf(dw, -1.0f), 1.0f);
        float angle_v = 2.0f * atan2f(vn, dwc);
        float scale   = (vn > TOLF) ? (angle_v / vn) : 0.0f;
        float wx = dx * scale * INV_DT;
        float wy = dy * scale * INV_DT;
        float wz = dz * scale * INV_DT;
        bool vv = vq[a] && vq[c] && isfinite(wx) && isfinite(wy) && isfinite(wz);
        wxo[i] = vv ? wx : 0.0f;
        wyo[i] = vv ? wy : 0.0f;
        wzo[i] = vv ? wz : 0.0f;

        float angle_d = 2.0f * atan2f(vn, dw);
        adst[i] = (vq[a] && vq[c] && isfinite(angle_d)) ? angle_d : 0.0f;
    }

    // ---- stores: 16 channels x float4, all coalesced ----
    *(float4*)(pout + 0  * TT + t0) = AX;
    *(float4*)(pout + 1  * TT + t0) = AY;
    *(float4*)(pout + 2  * TT + t0) = AZ;
    *(float4*)(pout + 3  * TT + t0) = QW;
    *(float4*)(pout + 4  * TT + t0) = QX;
    *(float4*)(pout + 5  * TT + t0) = QY;
    *(float4*)(pout + 6  * TT + t0) = QZ;
    *(float4*)(pout + 7  * TT + t0) = make_float4(lx[1], lx[2], lx[3], lx[4]);
    *(float4*)(pout + 8  * TT + t0) = make_float4(ly[1], ly[2], ly[3], ly[4]);
    *(float4*)(pout + 9  * TT + t0) = make_float4(lz[1], lz[2], lz[3], lz[4]);
    *(float4*)(pout + 10 * TT + t0) = make_float4(lam[1], lam[2], lam[3], lam[4]);
    *(float4*)(pout + 11 * TT + t0) = make_float4(jrk[0], jrk[1], jrk[2], jrk[3]);
    *(float4*)(pout + 12 * TT + t0) = make_float4(wxo[0], wxo[1], wxo[2], wxo[3]);
    *(float4*)(pout + 13 * TT + t0) = make_float4(wyo[0], wyo[1], wyo[2], wyo[3]);
    *(float4*)(pout + 14 * TT + t0) = make_float4(wzo[0], wzo[1], wzo[2], wzo[3]);
    *(float4*)(pout + 15 * TT + t0) = make_float4(adst[0], adst[1], adst[2], adst[3]);
}

extern "C" void kernel_launch(void* const* d_in, const int* in_sizes, int n_in,
                              void* d_out, int out_size) {
    (void)in_sizes; (void)n_in; (void)out_size;
    const float* in = (const float*)d_in[0];
    float* out = (float*)d_out;
    const int total_threads = NB * (TT / 4);   // 524288
    const int block = 256;
    const int grid = total_threads / block;    // 2048
    imu_feat_kernel<<<grid, block>>>(in, out);
}

// round 3
// speedup vs baseline: 1.3727x; 1.3727x over previous
#include <cuda_runtime.h>
#include <math.h>

// IMU feature extractor.
// in : (256, 7, 8192) f32   channels: ax ay az qw qx qy qz
// out: (256, 16, 8192) f32  channels: [imu 0-6][linacc 7-9][lam 10][jerk 11][angvel 12-14][angdist 15]

#define NB     256
#define TT     8192
#define TOL2F  1e-16f   // (1e-8)^2 : compare against squared norm
#define TOLF   1e-8f
#define INV_DT 200.0f

__global__ __launch_bounds__(256, 3)
void imu_feat_kernel(const float* __restrict__ in, float* __restrict__ out) {
    int tid = blockIdx.x * blockDim.x + threadIdx.x;
    int b  = tid >> 11;          // / 2048 vectors per batch-channel
    int t0 = (tid & 2047) * 4;

    const float* pin  = in  + (size_t)b * 7  * TT;
    float*       pout = out + (size_t)b * 16 * TT;

    // time index j: 0 -> t0-1, 1..4 -> t0..t0+3, 5 -> t0+4
    float ax[5], ay[5], az[5];
    float qw[6], qx[6], qy[6], qz[6];

    {
        // ---- loads: center float4 per channel + scalar halos ----
        float4 AX = *(const float4*)(pin + 0 * TT + t0);
        float4 AY = *(const float4*)(pin + 1 * TT + t0);
        float4 AZ = *(const float4*)(pin + 2 * TT + t0);
        float4 QW = *(const float4*)(pin + 3 * TT + t0);
        float4 QX = *(const float4*)(pin + 4 * TT + t0);
        float4 QY = *(const float4*)(pin + 5 * TT + t0);
        float4 QZ = *(const float4*)(pin + 6 * TT + t0);

        // passthrough stores NOW to shorten live ranges
        *(float4*)(pout + 0 * TT + t0) = AX;
        *(float4*)(pout + 1 * TT + t0) = AY;
        *(float4*)(pout + 2 * TT + t0) = AZ;
        *(float4*)(pout + 3 * TT + t0) = QW;
        *(float4*)(pout + 4 * TT + t0) = QX;
        *(float4*)(pout + 5 * TT + t0) = QY;
        *(float4*)(pout + 6 * TT + t0) = QZ;

        ax[1] = AX.x; ax[2] = AX.y; ax[3] = AX.z; ax[4] = AX.w;
        ay[1] = AY.x; ay[2] = AY.y; ay[3] = AY.z; ay[4] = AY.w;
        az[1] = AZ.x; az[2] = AZ.y; az[3] = AZ.z; az[4] = AZ.w;
        qw[1] = QW.x; qw[2] = QW.y; qw[3] = QW.z; qw[4] = QW.w;
        qx[1] = QX.x; qx[2] = QX.y; qx[3] = QX.z; qx[4] = QX.w;
        qy[1] = QY.x; qy[2] = QY.y; qy[3] = QY.z; qy[4] = QY.w;
        qz[1] = QZ.x; qz[2] = QZ.y; qz[3] = QZ.z; qz[4] = QZ.w;
    }

    {
        int tm = (t0 > 0) ? t0 - 1 : 0;            // halo for t0-1 (unused values gated)
        int tp = (t0 + 4 < TT) ? t0 + 4 : TT - 1;  // shift_next clamp
        ax[0] = pin[0 * TT + tm]; ay[0] = pin[1 * TT + tm]; az[0] = pin[2 * TT + tm];
        qw[0] = pin[3 * TT + tm]; qx[0] = pin[4 * TT + tm];
        qy[0] = pin[5 * TT + tm]; qz[0] = pin[6 * TT + tm];
        qw[5] = pin[3 * TT + tp]; qx[5] = pin[4 * TT + tp];
        qy[5] = pin[5 * TT + tp]; qz[5] = pin[6 * TT + tp];
    }

    // ---- normalize quaternions via rsqrt (validity: n^2 > (1e-8)^2) ----
    float nw[6], nx[6], ny[6], nz[6];
    bool  vq[6];
#pragma unroll
    for (int j = 0; j < 6; j++) {
        float n2 = qx[j] * qx[j] + qy[j] * qy[j] + qz[j] * qz[j] + qw[j] * qw[j];
        bool  v  = n2 > TOL2F;
        float inv = v ? rsqrtf(n2) : 1.0f;
        nx[j] = qx[j] * inv; ny[j] = qy[j] * inv;
        nz[j] = qz[j] * inv; nw[j] = qw[j] * inv;
        vq[j] = v;
    }

    // ---- gravity removal + linear-acc magnitude (j = 0..4 -> t0-1..t0+3) ----
    float lam[5];
    {
        float lx[5], ly[5], lz[5];
#pragma unroll
        for (int j = 0; j < 5; j++) {
            float gx = 19.62f * (nx[j] * nz[j] - nw[j] * ny[j]);
            float gy = 19.62f * (nw[j] * nx[j] + ny[j] * nz[j]);
            float gz = 9.81f - 19.62f * (nx[j] * nx[j] + ny[j] * ny[j]);
            float vx = vq[j] ? (ax[j] - gx) : ax[j];
            float vy = vq[j] ? (ay[j] - gy) : ay[j];
            float vz = vq[j] ? (az[j] - gz) : az[j];
            lx[j] = vx; ly[j] = vy; lz[j] = vz;
            lam[j] = sqrtf(vx * vx + vy * vy + vz * vz);
        }
        // store linear acc + lam + jerk now (frees lx/ly/lz)
        *(float4*)(pout + 7  * TT + t0) = make_float4(lx[1], lx[2], lx[3], lx[4]);
        *(float4*)(pout + 8  * TT + t0) = make_float4(ly[1], ly[2], ly[3], ly[4]);
        *(float4*)(pout + 9  * TT + t0) = make_float4(lz[1], lz[2], lz[3], lz[4]);
        *(float4*)(pout + 10 * TT + t0) = make_float4(lam[1], lam[2], lam[3], lam[4]);
        float j0 = (t0 > 0) ? (lam[1] - lam[0]) : 0.0f;
        *(float4*)(pout + 11 * TT + t0) =
            make_float4(j0, lam[2] - lam[1], lam[3] - lam[2], lam[4] - lam[3]);
    }

    // ---- delta-quaternion features (i = 0..3 -> t = t0+i) ----
    float wxo[4], wyo[4], wzo[4], adst[4];
#pragma unroll
    for (int i = 0; i < 4; i++) {
        const int a = i + 1, c = i + 2;  // q(t), q(t+1)
        float dot = nx[a] * nx[c] + ny[a] * ny[c] + nz[a] * nz[c] + nw[a] * nw[c];
        float s   = (dot < 0.0f) ? -1.0f : 1.0f;
        float x2 = nx[c] * s, y2 = ny[c] * s, z2 = nz[c] * s, w2 = nw[c] * s;

        float dx = nw[a] * x2 - nx[a] * w2 - ny[a] * z2 + nz[a] * y2;
        float dy = nw[a] * y2 + nx[a] * z2 - ny[a] * w2 - nz[a] * x2;
        float dz = nw[a] * z2 - nx[a] * y2 + ny[a] * x2 - nz[a] * w2;
        float dw = nw[a] * w2 + nx[a] * x2 + ny[a] * y2 + nz[a] * z2;
        // after the sign flip dw = |dot| >= 0, so clip(dw,-1,1) differs from dw
        // only by rounding eps at +1 -> one shared atan2 for angle_v and angle_d.

        float vn  = sqrtf(dx * dx + dy * dy + dz * dz);
        float ang = 2.0f * atan2f(vn, dw);
        float scale = (vn > TOLF) ? __fdividef(ang, vn) : 0.0f;
        float wx = dx * scale * INV_DT;
        float wy = dy * scale * INV_DT;
        float wz = dz * scale * INV_DT;
        bool vp = vq[a] && vq[c];
        bool vv = vp && isfinite(wx) && isfinite(wy) && isfinite(wz);
        wxo[i] = vv ? wx : 0.0f;
        wyo[i] = vv ? wy : 0.0f;
        wzo[i] = vv ? wz : 0.0f;
        adst[i] = (vp && isfinite(ang)) ? ang : 0.0f;
    }

    *(float4*)(pout + 12 * TT + t0) = make_float4(wxo[0], wxo[1], wxo[2], wxo[3]);
    *(float4*)(pout + 13 * TT + t0) = make_float4(wyo[0], wyo[1], wyo[2], wyo[3]);
    *(float4*)(pout + 14 * TT + t0) = make_float4(wzo[0], wzo[1], wzo[2], wzo[3]);
    *(float4*)(pout + 15 * TT + t0) = make_float4(adst[0], adst[1], adst[2], adst[3]);
}

extern "C" void kernel_launch(void* const* d_in, const int* in_sizes, int n_in,
                              void* d_out, int out_size) {
    (void)in_sizes; (void)n_in; (void)out_size;
    const float* in = (const float*)d_in[0];
    float* out = (float*)d_out;
    const int total_threads = NB * (TT / 4);   // 524288
    const int block = 256;
    const int grid = total_threads / block;    // 2048
    imu_feat_kernel<<<grid, block>>>(in, out);
}